// round 15
// baseline (speedup 1.0000x reference)
#include <cuda_runtime.h>
#include <cuda_fp16.h>
#include <math.h>
#include <stdint.h>

#define B_   4
#define L_   1024
#define DM   256
#define DI   512
#define NS   16
#define DTR  16
#define KC   4
#define NL   8
#define ROWS (B_*L_)
#define SEG  8
#define SEGLEN (L_/SEG)   // 128

// ---------------- static scratch (no allocs allowed) ----------------
__device__ float g_h[ROWS*DM];        // residual stream
__device__ float g_hidgate[ROWS*2*DI];// in-proj output: [hid | gate] (pre-conv)
__device__ float g_sp[ROWS*48];       // [dt(16) | B(16) | C(16)]
__device__ float g_delta[ROWS*DI];    // softplus(dt@Wdt+b) (seg1 -> seg2)
__device__ float g_y[ROWS*DI];        // scan output (gated)
__device__ float g_segP[B_*32*SEG*256];
__device__ float g_segH[B_*32*SEG*256];

// ---------------- f16-split helpers (identical to R14) ----------------
#define LO_SCALE    2048.0f
#define LO_UNSCALE  (1.0f/2048.0f)

__device__ __forceinline__ uint32_t pack_h2(float x, float y) {
    __half2 h = __floats2half2_rn(x, y);
    return *reinterpret_cast<uint32_t*>(&h);
}
__device__ __forceinline__ void split_f16(float x, float& hi, float& lo) {
    hi = __half2float(__float2half_rn(x));
    lo = (x - hi) * LO_SCALE;
}
__device__ __forceinline__ void mma_f16(float* c,
                                        uint32_t a0, uint32_t a1, uint32_t a2, uint32_t a3,
                                        uint32_t b0, uint32_t b1) {
    asm volatile(
        "mma.sync.aligned.m16n8k16.row.col.f32.f16.f16.f32 "
        "{%0,%1,%2,%3}, {%4,%5,%6,%7}, {%8,%9}, {%0,%1,%2,%3};"
        : "+f"(c[0]), "+f"(c[1]), "+f"(c[2]), "+f"(c[3])
        : "r"(a0), "r"(a1), "r"(a2), "r"(a3), "r"(b0), "r"(b1));
}
__device__ __forceinline__ float silu_f(float a) {
    return a / (1.f + __expf(-a));
}

// ======== shared GEMM mainloop/epilogue pieces (R14-identical math) ========
// mainloop over one staged chunk; B staging helper shared.
template<int N_, int K_>
__device__ __forceinline__ void stage_B_chunk(uint32_t (*Bsh)[20], uint32_t (*Bsl)[20],
                                              const float* __restrict__ Bw,
                                              int k0, int col0, int tid) {
    #pragma unroll
    for (int it = 0; it < 2; it++) {
        int idx = tid + it*256;
        int kp = idx & 15, np = idx >> 4;
        int gn = col0 + np*2;
        float2 v0, v1;
        if ((N_ & 63) == 0 || gn < N_) {
            v0 = *reinterpret_cast<const float2*>(Bw + (size_t)(k0 + 2*kp    )*N_ + gn);
            v1 = *reinterpret_cast<const float2*>(Bw + (size_t)(k0 + 2*kp + 1)*N_ + gn);
        } else {
            v0 = make_float2(0.f, 0.f);
            v1 = v0;
        }
        float h00,l00,h10,l10,h01,l01,h11,l11;
        split_f16(v0.x, h00, l00);
        split_f16(v1.x, h10, l10);
        split_f16(v0.y, h01, l01);
        split_f16(v1.y, h11, l11);
        Bsh[np*2    ][kp] = pack_h2(h00, h10);
        Bsh[np*2 + 1][kp] = pack_h2(h01, h11);
        Bsl[np*2    ][kp] = pack_h2(l00, l10);
        Bsl[np*2 + 1][kp] = pack_h2(l01, l11);
    }
}

__device__ __forceinline__ void gemm_mainloop(uint32_t (*Ash)[20], uint32_t (*Asl)[20],
                                              uint32_t (*Bsh)[20], uint32_t (*Bsl)[20],
                                              float (*acc)[4], float (*acc2)[4],
                                              int wr, int wc, int g, int t) {
    #pragma unroll
    for (int ks = 0; ks < 2; ks++) {
        const int rb = wr*16 + g;
        const int kb = ks*8 + t;
        uint32_t ah0 = Ash[rb    ][kb    ], ah1 = Ash[rb + 8][kb    ];
        uint32_t ah2 = Ash[rb    ][kb + 4], ah3 = Ash[rb + 8][kb + 4];
        uint32_t al0 = Asl[rb    ][kb    ], al1 = Asl[rb + 8][kb    ];
        uint32_t al2 = Asl[rb    ][kb + 4], al3 = Asl[rb + 8][kb + 4];
        #pragma unroll
        for (int nt = 0; nt < 4; nt++) {
            const int cb = wc*32 + nt*8 + g;
            uint32_t bh0 = Bsh[cb][kb], bh1 = Bsh[cb][kb + 4];
            uint32_t bl0 = Bsl[cb][kb], bl1 = Bsl[cb][kb + 4];
            mma_f16(acc [nt], ah0, ah1, ah2, ah3, bh0, bh1);
            mma_f16(acc2[nt], ah0, ah1, ah2, ah3, bl0, bl1);
            mma_f16(acc2[nt], al0, al1, al2, al3, bh0, bh1);
        }
    }
}

template<int N_, bool RES>
__device__ __forceinline__ void gemm_epilogue(float (*acc)[4], float (*acc2)[4],
                                              float* C, const float* Res,
                                              int row0, int col0,
                                              int wr, int wc, int g, int t) {
    const int r0 = row0 + wr*16 + g;
    #pragma unroll
    for (int nt = 0; nt < 4; nt++) {
        const int cbase = col0 + wc*32 + nt*8 + 2*t;
        #pragma unroll
        for (int h = 0; h < 2; h++) {
            int gm = r0 + h*8;
            #pragma unroll
            for (int q = 0; q < 2; q++) {
                int gn = cbase + q;
                if ((N_ & 63) == 0 || gn < N_) {
                    float v = fmaf(acc2[nt][h*2 + q], LO_UNSCALE, acc[nt][h*2 + q]);
                    if (RES) v += Res[(size_t)gm*N_ + gn];
                    C[(size_t)gm*N_ + gn] = v;
                }
            }
        }
    }
}

// ================= gemm_in: rmsnorm FUSED (A = rmsnorm(g_h)) =================
__global__ void __launch_bounds__(256) gemm_in_k(const float* __restrict__ W,
                                                 const float* __restrict__ lnw) {
    constexpr int N_ = 2*DI, K_ = DM;
    __shared__ uint32_t Ash[64][20], Asl[64][20], Bsh[64][20], Bsl[64][20];
    __shared__ float sScale[64];
    __shared__ float sW[DM];
    const int tid  = threadIdx.x;
    const int lane = tid & 31;
    const int warp = tid >> 5;
    const int wr   = warp & 3;
    const int wc   = warp >> 2;
    const int g    = lane >> 2;
    const int t    = lane & 3;
    const int row0 = blockIdx.y * 64;
    const int col0 = blockIdx.x * 64;

    sW[tid] = lnw[tid];   // 256 threads, DM=256
    // row scales (rmsnorm, same reduction order as R14 rmsnorm kernel)
    #pragma unroll
    for (int i = 0; i < 8; i++) {
        int r = warp*8 + i;
        const float* src = g_h + (size_t)(row0 + r) * DM;
        float4 v0 = *reinterpret_cast<const float4*>(src + lane * 4);
        float4 v1 = *reinterpret_cast<const float4*>(src + 128 + lane * 4);
        float ss = v0.x*v0.x + v0.y*v0.y + v0.z*v0.z + v0.w*v0.w
                 + v1.x*v1.x + v1.y*v1.y + v1.z*v1.z + v1.w*v1.w;
        #pragma unroll
        for (int o = 16; o > 0; o >>= 1) ss += __shfl_xor_sync(0xffffffffu, ss, o);
        if (lane == 0) sScale[r] = rsqrtf(ss * (1.f/DM) + 1e-5f);
    }
    __syncthreads();

    float acc[4][4], acc2[4][4];
    #pragma unroll
    for (int nt = 0; nt < 4; nt++)
        #pragma unroll
        for (int q = 0; q < 4; q++) { acc[nt][q] = 0.f; acc2[nt][q] = 0.f; }

    for (int k0 = 0; k0 < K_; k0 += 32) {
        #pragma unroll
        for (int it = 0; it < 2; it++) {
            int idx = tid + it*256;
            int r = idx >> 3, k4 = idx & 7;
            float4 v = *reinterpret_cast<const float4*>(
                g_h + (size_t)(row0 + r)*K_ + k0 + k4*4);
            float sc = sScale[r];
            float vx = v.x * sc * sW[k0 + k4*4 + 0];
            float vy = v.y * sc * sW[k0 + k4*4 + 1];
            float vz = v.z * sc * sW[k0 + k4*4 + 2];
            float vw = v.w * sc * sW[k0 + k4*4 + 3];
            float hx,lx,hy,ly,hz,lz,hw,lw;
            split_f16(vx, hx, lx);
            split_f16(vy, hy, ly);
            split_f16(vz, hz, lz);
            split_f16(vw, hw, lw);
            Ash[r][k4*2    ] = pack_h2(hx, hy);
            Ash[r][k4*2 + 1] = pack_h2(hz, hw);
            Asl[r][k4*2    ] = pack_h2(lx, ly);
            Asl[r][k4*2 + 1] = pack_h2(lz, lw);
        }
        stage_B_chunk<N_, K_>(Bsh, Bsl, W, k0, col0, tid);
        __syncthreads();
        gemm_mainloop(Ash, Asl, Bsh, Bsl, acc, acc2, wr, wc, g, t);
        __syncthreads();
    }
    gemm_epilogue<N_, false>(acc, acc2, g_hidgate, nullptr, row0, col0, wr, wc, g, t);
}

// ================= gemm_x: conv+silu FUSED (A = silu(conv(hidgate))) =================
__global__ void __launch_bounds__(256) gemm_x_k(const float* __restrict__ W,
                                                const float* __restrict__ cw,
                                                const float* __restrict__ cb) {
    constexpr int N_ = 48, K_ = DI;
    __shared__ uint32_t Ash[64][20], Asl[64][20], Bsh[64][20], Bsl[64][20];
    __shared__ float4 sCW[DI];
    __shared__ float  sCB[DI];
    const int tid  = threadIdx.x;
    const int lane = tid & 31;
    const int warp = tid >> 5;
    const int wr   = warp & 3;
    const int wc   = warp >> 2;
    const int g    = lane >> 2;
    const int t    = lane & 3;
    const int row0 = blockIdx.y * 64;
    const int col0 = blockIdx.x * 64;

    #pragma unroll
    for (int i = tid; i < DI; i += 256) {
        sCW[i] = *reinterpret_cast<const float4*>(cw + i*KC);
        sCB[i] = cb[i];
    }
    __syncthreads();

    float acc[4][4], acc2[4][4];
    #pragma unroll
    for (int nt = 0; nt < 4; nt++)
        #pragma unroll
        for (int q = 0; q < 4; q++) { acc[nt][q] = 0.f; acc2[nt][q] = 0.f; }

    for (int k0 = 0; k0 < K_; k0 += 32) {
        #pragma unroll
        for (int it = 0; it < 2; it++) {
            int idx = tid + it*256;
            int r = idx >> 3, k4 = idx & 7;
            int gr = row0 + r;
            int l  = gr & (L_-1);
            int ch = k0 + k4*4;
            const float* bp = g_hidgate + (size_t)gr*(2*DI) + ch;
            const float4 zero = make_float4(0.f, 0.f, 0.f, 0.f);
            float4 x0  = *reinterpret_cast<const float4*>(bp);
            float4 xm1 = (l >= 1) ? *reinterpret_cast<const float4*>(bp - 1*2*DI) : zero;
            float4 xm2 = (l >= 2) ? *reinterpret_cast<const float4*>(bp - 2*2*DI) : zero;
            float4 xm3 = (l >= 3) ? *reinterpret_cast<const float4*>(bp - 3*2*DI) : zero;
            float4 w0 = sCW[ch+0], w1 = sCW[ch+1], w2 = sCW[ch+2], w3 = sCW[ch+3];
            float ax = fmaf(x0.x, w0.w, fmaf(xm1.x, w0.z, fmaf(xm2.x, w0.y, fmaf(xm3.x, w0.x, sCB[ch+0]))));
            float ay = fmaf(x0.y, w1.w, fmaf(xm1.y, w1.z, fmaf(xm2.y, w1.y, fmaf(xm3.y, w1.x, sCB[ch+1]))));
            float az = fmaf(x0.z, w2.w, fmaf(xm1.z, w2.z, fmaf(xm2.z, w2.y, fmaf(xm3.z, w2.x, sCB[ch+2]))));
            float aw = fmaf(x0.w, w3.w, fmaf(xm1.w, w3.z, fmaf(xm2.w, w3.y, fmaf(xm3.w, w3.x, sCB[ch+3]))));
            float vx = silu_f(ax), vy = silu_f(ay), vz = silu_f(az), vw = silu_f(aw);
            float hx,lx,hy,ly,hz,lz,hw,lw;
            split_f16(vx, hx, lx);
            split_f16(vy, hy, ly);
            split_f16(vz, hz, lz);
            split_f16(vw, hw, lw);
            Ash[r][k4*2    ] = pack_h2(hx, hy);
            Ash[r][k4*2 + 1] = pack_h2(hz, hw);
            Asl[r][k4*2    ] = pack_h2(lx, ly);
            Asl[r][k4*2 + 1] = pack_h2(lz, lw);
        }
        stage_B_chunk<N_, K_>(Bsh, Bsl, W, k0, col0, tid);
        __syncthreads();
        gemm_mainloop(Ash, Asl, Bsh, Bsl, acc, acc2, wr, wc, g, t);
        __syncthreads();
    }
    gemm_epilogue<N_, false>(acc, acc2, g_sp, nullptr, row0, col0, wr, wc, g, t);
}

// ================= gemm_out: identical to R14 =================
__global__ void __launch_bounds__(256) gemm_out_k(const float* __restrict__ W) {
    constexpr int N_ = DM, K_ = DI;
    __shared__ uint32_t Ash[64][20], Asl[64][20], Bsh[64][20], Bsl[64][20];
    const int tid  = threadIdx.x;
    const int lane = tid & 31;
    const int warp = tid >> 5;
    const int wr   = warp & 3;
    const int wc   = warp >> 2;
    const int g    = lane >> 2;
    const int t    = lane & 3;
    const int row0 = blockIdx.y * 64;
    const int col0 = blockIdx.x * 64;

    float acc[4][4], acc2[4][4];
    #pragma unroll
    for (int nt = 0; nt < 4; nt++)
        #pragma unroll
        for (int q = 0; q < 4; q++) { acc[nt][q] = 0.f; acc2[nt][q] = 0.f; }

    for (int k0 = 0; k0 < K_; k0 += 32) {
        #pragma unroll
        for (int it = 0; it < 2; it++) {
            int idx = tid + it*256;
            int r = idx >> 3, k4 = idx & 7;
            float4 v = *reinterpret_cast<const float4*>(
                g_y + (size_t)(row0 + r)*K_ + k0 + k4*4);
            float hx,lx,hy,ly,hz,lz,hw,lw;
            split_f16(v.x, hx, lx);
            split_f16(v.y, hy, ly);
            split_f16(v.z, hz, lz);
            split_f16(v.w, hw, lw);
            Ash[r][k4*2    ] = pack_h2(hx, hy);
            Ash[r][k4*2 + 1] = pack_h2(hz, hw);
            Asl[r][k4*2    ] = pack_h2(lx, ly);
            Asl[r][k4*2 + 1] = pack_h2(lz, lw);
        }
        stage_B_chunk<N_, K_>(Bsh, Bsl, W, k0, col0, tid);
        __syncthreads();
        gemm_mainloop(Ash, Asl, Bsh, Bsl, acc, acc2, wr, wc, g, t);
        __syncthreads();
    }
    gemm_epilogue<N_, true>(acc, acc2, g_h, g_h, row0, col0, wr, wc, g, t);
}

// ---------------- embed ----------------
__global__ void embed_kernel(const float* __restrict__ x,
                             const float* __restrict__ pos,
                             const float* __restrict__ We,
                             const float* __restrict__ be) {
    int row = blockIdx.x;
    int j   = threadIdx.x;
    int l   = row & (L_-1);
    float x0 = x[row*2+0], x1 = x[row*2+1];
    g_h[(size_t)row*DM + j]       = x0*We[j] + x1*We[128+j] + be[j];
    g_h[(size_t)row*DM + 128 + j] = pos[l*128 + j];
}

// ---------------- conv-on-the-fly for scan staging ----------------
__device__ __forceinline__ float conv_silu_one(int row, int l, int ch,
                                               float4 w4, float bias) {
    const float* bp = g_hidgate + (size_t)row*(2*DI) + ch;
    float x0  = bp[0];
    float xm1 = (l >= 1) ? bp[-1*2*DI] : 0.f;
    float xm2 = (l >= 2) ? bp[-2*2*DI] : 0.f;
    float xm3 = (l >= 3) ? bp[-3*2*DI] : 0.f;
    float a = fmaf(x0, w4.w, fmaf(xm1, w4.z, fmaf(xm2, w4.y, fmaf(xm3, w4.x, bias))));
    return silu_f(a);
}

// ---------------- scan pass 1: summaries; conv+delta fused; stores delta ------
#define CH 16
__global__ void __launch_bounds__(256) scan_seg1(const float* __restrict__ Alog,
                                                 const float* __restrict__ Wdt,
                                                 const float* __restrict__ bdt,
                                                 const float* __restrict__ cw,
                                                 const float* __restrict__ cb) {
    const int s    = blockIdx.x & (SEG-1);
    const int dblk = (blockIdx.x >> 3) & 31;
    const int b    = blockIdx.x >> 8;
    const int tid  = threadIdx.x;
    const int n    = tid & 15;
    const int dl   = tid >> 4;
    const int d    = dblk*16 + dl;
    const float A  = -__expf(Alog[d*NS + n]);
    float h = 0.f, P = 1.f;
    __shared__ float s_Wdt[DTR][17], s_bdt[16];
    __shared__ float4 s_cw4[16];
    __shared__ float s_cb[16];
    __shared__ float s_dt[CH][16], s_delta[CH][16], s_hid[CH][16], s_B[CH][16];
    {
        int r = tid >> 4, c = tid & 15;
        s_Wdt[r][c] = Wdt[r*DI + dblk*16 + c];
        if (tid < 16) {
            s_bdt[tid] = bdt[dblk*16 + tid];
            s_cw4[tid] = *reinterpret_cast<const float4*>(cw + (dblk*16 + tid)*KC);
            s_cb[tid]  = cb[dblk*16 + tid];
        }
    }
    __syncthreads();
    const int tbase = b*L_ + s*SEGLEN;
    for (int t0 = 0; t0 < SEGLEN; t0 += CH) {
        __syncthreads();
        {
            int tt = tid >> 4, c = tid & 15;
            int row = tbase + t0 + tt;
            int l   = row & (L_-1);
            s_dt[tt][c]  = g_sp[row*48 + c];
            s_hid[tt][c] = conv_silu_one(row, l, dblk*16 + c, s_cw4[c], s_cb[c]);
            s_B[tt][c]   = g_sp[row*48 + DTR + c];
        }
        __syncthreads();
        {
            int tt = tid >> 4, c = tid & 15;
            float acc = s_bdt[c];
            #pragma unroll
            for (int r = 0; r < DTR; r++) acc = fmaf(s_dt[tt][r], s_Wdt[r][c], acc);
            float de = (acc > 20.f) ? acc : log1pf(__expf(acc));
            s_delta[tt][c] = de;
            int row = tbase + t0 + tt;
            g_delta[(size_t)row*DI + dblk*16 + c] = de;
        }
        __syncthreads();
        #pragma unroll
        for (int tt = 0; tt < CH; tt++) {
            float de  = s_delta[tt][dl];
            float dA  = __expf(de * A);
            float dBu = de * s_B[tt][n] * s_hid[tt][dl];
            h = fmaf(dA, h, dBu);
            P *= dA;
        }
    }
    int idx = ((b*32 + dblk)*SEG + s)*256 + tid;
    g_segP[idx] = P;
    g_segH[idx] = h;
}

// ---------------- scan pass 2: replay; conv fused; delta loaded ----------------
__global__ void __launch_bounds__(256) scan_seg2(const float* __restrict__ Alog,
                                                 const float* __restrict__ Dsk,
                                                 const float* __restrict__ cw,
                                                 const float* __restrict__ cb) {
    const int s    = blockIdx.x & (SEG-1);
    const int dblk = (blockIdx.x >> 3) & 31;
    const int b    = blockIdx.x >> 8;
    const int tid  = threadIdx.x;
    const int n    = tid & 15;
    const int dl   = tid >> 4;
    const int d    = dblk*16 + dl;
    const float A  = -__expf(Alog[d*NS + n]);
    const float Dskip = Dsk[d];

    float h = 0.f;
    {
        const int base = (b*32 + dblk)*SEG;
        float Ps[SEG-1], Hs[SEG-1];
        #pragma unroll
        for (int ss = 0; ss < SEG-1; ss++) {
            if (ss < s) {
                int idx = (base + ss)*256 + tid;
                Ps[ss] = g_segP[idx];
                Hs[ss] = g_segH[idx];
            }
        }
        #pragma unroll
        for (int ss = 0; ss < SEG-1; ss++)
            if (ss < s) h = fmaf(Ps[ss], h, Hs[ss]);
    }

    __shared__ float4 s_cw4[16];
    __shared__ float s_cb[16];
    __shared__ float s_delta[CH][16], s_hid[CH][16], s_B[CH][16],
                     s_C[CH][16], s_gate[CH][16], s_y[CH][16];
    if (tid < 16) {
        s_cw4[tid] = *reinterpret_cast<const float4*>(cw + (dblk*16 + tid)*KC);
        s_cb[tid]  = cb[dblk*16 + tid];
    }
    __syncthreads();
    const int tbase = b*L_ + s*SEGLEN;
    for (int t0 = 0; t0 < SEGLEN; t0 += CH) {
        __syncthreads();
        {
            int tt = tid >> 4, c = tid & 15;
            int row = tbase + t0 + tt;
            int l   = row & (L_-1);
            s_delta[tt][c] = g_delta[(size_t)row*DI + dblk*16 + c];
            s_hid[tt][c]   = conv_silu_one(row, l, dblk*16 + c, s_cw4[c], s_cb[c]);
            s_B[tt][c]     = g_sp[row*48 + DTR + c];
            s_C[tt][c]     = g_sp[row*48 + DTR + NS + c];
            s_gate[tt][c]  = g_hidgate[(size_t)row*(2*DI) + DI + dblk*16 + c];
        }
        __syncthreads();
        #pragma unroll
        for (int tt = 0; tt < CH; tt++) {
            float de  = s_delta[tt][dl];
            float dA  = __expf(de * A);
            float dBu = de * s_B[tt][n] * s_hid[tt][dl];
            h = fmaf(dA, h, dBu);
            float contrib = h * s_C[tt][n];
            contrib += __shfl_xor_sync(0xffffffffu, contrib, 1);
            contrib += __shfl_xor_sync(0xffffffffu, contrib, 2);
            contrib += __shfl_xor_sync(0xffffffffu, contrib, 4);
            contrib += __shfl_xor_sync(0xffffffffu, contrib, 8);
            if (n == 0) {
                float yv = contrib + s_hid[tt][dl]*Dskip;
                float g  = s_gate[tt][dl];
                s_y[tt][dl] = yv * g / (1.f + __expf(-g));
            }
        }
        __syncthreads();
        {
            int tt = tid >> 4, c = tid & 15;
            int row = tbase + t0 + tt;
            g_y[(size_t)row*DI + dblk*16 + c] = s_y[tt][c];
        }
    }
}

// ---------------- output head ----------------
__global__ void __launch_bounds__(256) head_kernel(const float* __restrict__ Wa,
                                                   const float* __restrict__ ba,
                                                   const float* __restrict__ Wp,
                                                   const float* __restrict__ bp,
                                                   float* __restrict__ out) {
    int row = blockIdx.x, tid = threadIdx.x;
    float v  = g_h[(size_t)row*DM + tid];
    float pa = v * Wa[tid];
    float pp = v * Wp[tid];
    #pragma unroll
    for (int o = 16; o > 0; o >>= 1) {
        pa += __shfl_xor_sync(0xffffffffu, pa, o);
        pp += __shfl_xor_sync(0xffffffffu, pp, o);
    }
    __shared__ float ra[8], rp[8];
    if ((tid & 31) == 0) { ra[tid>>5] = pa; rp[tid>>5] = pp; }
    __syncthreads();
    if (tid == 0) {
        float sa = 0.f, sp2 = 0.f;
        #pragma unroll
        for (int i = 0; i < 8; i++) { sa += ra[i]; sp2 += rp[i]; }
        out[row*2+0] = sa + ba[0];
        out[row*2+1] = tanhf(sp2 + bp[0]);
    }
}

// ---------------- launch ----------------
extern "C" void kernel_launch(void* const* d_in, const int* in_sizes, int n_in,
                              void* d_out, int out_size) {
    const float* x       = (const float*)d_in[0];
    const float* pos     = (const float*)d_in[1];
    const float* W_embed = (const float*)d_in[2];
    const float* b_embed = (const float*)d_in[3];
    const float* ln_w    = (const float*)d_in[4];
    const float* W_in    = (const float*)d_in[5];
    const float* conv_w  = (const float*)d_in[6];
    const float* conv_b  = (const float*)d_in[7];
    const float* W_x     = (const float*)d_in[8];
    const float* W_dt    = (const float*)d_in[9];
    const float* b_dt    = (const float*)d_in[10];
    const float* A_log   = (const float*)d_in[11];
    const float* D_skip  = (const float*)d_in[12];
    const float* W_out   = (const float*)d_in[13];
    const float* W_amp   = (const float*)d_in[14];
    const float* b_amp   = (const float*)d_in[15];
    const float* W_phase = (const float*)d_in[16];
    const float* b_phase = (const float*)d_in[17];

    embed_kernel<<<ROWS, 128>>>(x, pos, W_embed, b_embed);

    for (int i = 0; i < NL; i++) {
        gemm_in_k<<<dim3((2*DI)/64, ROWS/64), 256>>>(W_in + (size_t)i*DM*2*DI,
                                                     ln_w + (size_t)i*DM);
        gemm_x_k<<<dim3(1, ROWS/64), 256>>>(W_x + (size_t)i*DI*48,
                                            conv_w + (size_t)i*DI*KC,
                                            conv_b + (size_t)i*DI);
        scan_seg1<<<B_*32*SEG, 256>>>(A_log + (size_t)i*DI*NS,
                                      W_dt + (size_t)i*DTR*DI,
                                      b_dt + (size_t)i*DI,
                                      conv_w + (size_t)i*DI*KC,
                                      conv_b + (size_t)i*DI);
        scan_seg2<<<B_*32*SEG, 256>>>(A_log + (size_t)i*DI*NS,
                                      D_skip + (size_t)i*DI,
                                      conv_w + (size_t)i*DI*KC,
                                      conv_b + (size_t)i*DI);
        gemm_out_k<<<dim3(DM/64, ROWS/64), 256>>>(W_out + (size_t)i*DI*DM);
    }

    head_kernel<<<ROWS, 256>>>(W_amp, b_amp, W_phase, b_phase, (float*)d_out);
}

// round 16
// speedup vs baseline: 1.0543x; 1.0543x over previous
#include <cuda_runtime.h>
#include <cuda_fp16.h>
#include <math.h>
#include <stdint.h>

#define B_   4
#define L_   1024
#define DM   256
#define DI   512
#define NS   16
#define DTR  16
#define KC   4
#define NL   8
#define ROWS (B_*L_)
#define SEG  8
#define SEGLEN (L_/SEG)   // 128

// ---------------- static scratch (no allocs allowed) ----------------
__device__ float g_h[ROWS*DM];        // residual stream
__device__ float g_hidgate[ROWS*2*DI];// in-proj output: [hid | gate]
__device__ float g_hid[ROWS*DI];      // post conv+silu
__device__ float g_sp[ROWS*48];       // [dt(16) | B(16) | C(16)]
__device__ float g_delta[ROWS*DI];    // softplus(dt@Wdt+b), seg1 -> seg2
__device__ float g_y[ROWS*DI];        // scan output (gated)
__device__ float g_segP[B_*32*SEG*256];
__device__ float g_segH[B_*32*SEG*256];

// ---------------- f16-split helpers (identical to R14) ----------------
#define LO_SCALE    2048.0f
#define LO_UNSCALE  (1.0f/2048.0f)

__device__ __forceinline__ uint32_t pack_h2(float x, float y) {
    __half2 h = __floats2half2_rn(x, y);
    return *reinterpret_cast<uint32_t*>(&h);
}
__device__ __forceinline__ void split_f16(float x, float& hi, float& lo) {
    hi = __half2float(__float2half_rn(x));
    lo = (x - hi) * LO_SCALE;
}
__device__ __forceinline__ void mma_f16(float* c,
                                        uint32_t a0, uint32_t a1, uint32_t a2, uint32_t a3,
                                        uint32_t b0, uint32_t b1) {
    asm volatile(
        "mma.sync.aligned.m16n8k16.row.col.f32.f16.f16.f32 "
        "{%0,%1,%2,%3}, {%4,%5,%6,%7}, {%8,%9}, {%0,%1,%2,%3};"
        : "+f"(c[0]), "+f"(c[1]), "+f"(c[2]), "+f"(c[3])
        : "r"(a0), "r"(a1), "r"(a2), "r"(a3), "r"(b0), "r"(b1));
}

__device__ __forceinline__ void stage_A_word(uint32_t (*Ash)[20], uint32_t (*Asl)[20],
                                             int r, int k4, float4 v) {
    float hx,lx,hy,ly,hz,lz,hw,lw;
    split_f16(v.x, hx, lx);
    split_f16(v.y, hy, ly);
    split_f16(v.z, hz, lz);
    split_f16(v.w, hw, lw);
    Ash[r][k4*2    ] = pack_h2(hx, hy);
    Ash[r][k4*2 + 1] = pack_h2(hz, hw);
    Asl[r][k4*2    ] = pack_h2(lx, ly);
    Asl[r][k4*2 + 1] = pack_h2(lz, lw);
}

// ================= 128xBN f16-split GEMM, 512 threads =================
// C[M,N_] = A[M,K_] @ W[K_,N_] (+Res). Warp grid 4x4: warp covers 32 rows x BN/4 cols.
// DO_RMS: A := rmsnorm(A-rows)*lnw (validated in R15).
template<int BN, int N_, int K_, bool RES, bool DO_RMS>
__device__ __forceinline__ void gemm128_body(const float* __restrict__ A,
                                             const float* __restrict__ W,
                                             float* C, const float* Res,
                                             const float* lnw) {
    constexpr int NT = BN / 32;
    __shared__ uint32_t Ash[128][20], Asl[128][20];
    __shared__ uint32_t Bsh[BN][20],  Bsl[BN][20];
    __shared__ float sScale[128];
    __shared__ float sW[DM];
    const int tid  = threadIdx.x;      // 0..511
    const int lane = tid & 31;
    const int warp = tid >> 5;         // 0..15
    const int wr   = warp & 3;         // 32-row group
    const int wc   = warp >> 2;        // BN/4-col group
    const int g    = lane >> 2;
    const int t    = lane & 3;
    const int row0 = blockIdx.y * 128;
    const int col0 = blockIdx.x * BN;

    if (DO_RMS) {
        if (tid < DM) sW[tid] = lnw[tid];
        #pragma unroll
        for (int i = 0; i < 8; i++) {
            int r = warp*8 + i;        // 16 warps x 8 rows = 128
            const float* src = A + (size_t)(row0 + r) * DM;
            float4 v0 = *reinterpret_cast<const float4*>(src + lane * 4);
            float4 v1 = *reinterpret_cast<const float4*>(src + 128 + lane * 4);
            float ss = v0.x*v0.x + v0.y*v0.y + v0.z*v0.z + v0.w*v0.w
                     + v1.x*v1.x + v1.y*v1.y + v1.z*v1.z + v1.w*v1.w;
            #pragma unroll
            for (int o = 16; o > 0; o >>= 1) ss += __shfl_xor_sync(0xffffffffu, ss, o);
            if (lane == 0) sScale[r] = rsqrtf(ss * (1.f/DM) + 1e-5f);
        }
        __syncthreads();
    }

    float acc[2][NT][4], acc2[2][NT][4];
    #pragma unroll
    for (int mt = 0; mt < 2; mt++)
        #pragma unroll
        for (int nt = 0; nt < NT; nt++)
            #pragma unroll
            for (int q = 0; q < 4; q++) { acc[mt][nt][q] = 0.f; acc2[mt][nt][q] = 0.f; }

    for (int k0 = 0; k0 < K_; k0 += 32) {
        // ---- stage A: 128 rows x 8 k4-groups = 1024 units, 2/thread ----
        #pragma unroll
        for (int it = 0; it < 2; it++) {
            int idx = tid + it*512;
            int r = idx >> 3, k4 = idx & 7;
            float4 v = *reinterpret_cast<const float4*>(
                A + (size_t)(row0 + r)*K_ + k0 + k4*4);
            if (DO_RMS) {
                float sc = sScale[r];
                v.x = v.x * sc * sW[k0 + k4*4 + 0];
                v.y = v.y * sc * sW[k0 + k4*4 + 1];
                v.z = v.z * sc * sW[k0 + k4*4 + 2];
                v.w = v.w * sc * sW[k0 + k4*4 + 3];
            }
            stage_A_word(Ash, Asl, r, k4, v);
        }
        // ---- stage B: 16 kp x BN/2 np = 8*BN units ----
        #pragma unroll
        for (int it = 0; it < (8*BN)/512; it++) {
            int idx = tid + it*512;
            int kp = idx & 15, np = idx >> 4;
            int gn = col0 + np*2;
            float2 v0, v1;
            if ((N_ % BN) == 0 || gn < N_) {
                v0 = *reinterpret_cast<const float2*>(W + (size_t)(k0 + 2*kp    )*N_ + gn);
                v1 = *reinterpret_cast<const float2*>(W + (size_t)(k0 + 2*kp + 1)*N_ + gn);
            } else {
                v0 = make_float2(0.f, 0.f);
                v1 = v0;
            }
            float h00,l00,h10,l10,h01,l01,h11,l11;
            split_f16(v0.x, h00, l00);
            split_f16(v1.x, h10, l10);
            split_f16(v0.y, h01, l01);
            split_f16(v1.y, h11, l11);
            Bsh[np*2    ][kp] = pack_h2(h00, h10);
            Bsh[np*2 + 1][kp] = pack_h2(h01, h11);
            Bsl[np*2    ][kp] = pack_h2(l00, l10);
            Bsl[np*2 + 1][kp] = pack_h2(l01, l11);
        }
        __syncthreads();

        // ---- mainloop ----
        #pragma unroll
        for (int ks = 0; ks < 2; ks++) {
            const int kb = ks*8 + t;
            #pragma unroll
            for (int mt = 0; mt < 2; mt++) {
                const int rb = wr*32 + mt*16 + g;
                uint32_t ah0 = Ash[rb    ][kb    ], ah1 = Ash[rb + 8][kb    ];
                uint32_t ah2 = Ash[rb    ][kb + 4], ah3 = Ash[rb + 8][kb + 4];
                uint32_t al0 = Asl[rb    ][kb    ], al1 = Asl[rb + 8][kb    ];
                uint32_t al2 = Asl[rb    ][kb + 4], al3 = Asl[rb + 8][kb + 4];
                #pragma unroll
                for (int nt = 0; nt < NT; nt++) {
                    const int cb = wc*(BN/4) + nt*8 + g;
                    uint32_t bh0 = Bsh[cb][kb], bh1 = Bsh[cb][kb + 4];
                    uint32_t bl0 = Bsl[cb][kb], bl1 = Bsl[cb][kb + 4];
                    mma_f16(acc [mt][nt], ah0, ah1, ah2, ah3, bh0, bh1);
                    mma_f16(acc2[mt][nt], ah0, ah1, ah2, ah3, bl0, bl1);
                    mma_f16(acc2[mt][nt], al0, al1, al2, al3, bh0, bh1);
                }
            }
        }
        __syncthreads();
    }

    // ---- epilogue ----
    #pragma unroll
    for (int mt = 0; mt < 2; mt++) {
        const int r0 = row0 + wr*32 + mt*16 + g;
        #pragma unroll
        for (int nt = 0; nt < NT; nt++) {
            const int cbase = col0 + wc*(BN/4) + nt*8 + 2*t;
            #pragma unroll
            for (int h = 0; h < 2; h++) {
                int gm = r0 + h*8;
                #pragma unroll
                for (int q = 0; q < 2; q++) {
                    int gn = cbase + q;
                    if ((N_ % BN) == 0 || gn < N_) {
                        float v = fmaf(acc2[mt][nt][h*2 + q], LO_UNSCALE, acc[mt][nt][h*2 + q]);
                        if (RES) v += Res[(size_t)gm*N_ + gn];
                        C[(size_t)gm*N_ + gn] = v;
                    }
                }
            }
        }
    }
}

__global__ void __launch_bounds__(512) gemm_in_k(const float* __restrict__ W,
                                                 const float* __restrict__ lnw) {
    gemm128_body<128, 2*DI, DM, false, true>(g_h, W, g_hidgate, nullptr, lnw);
}
__global__ void __launch_bounds__(512) gemm_x_k(const float* __restrict__ W) {
    gemm128_body<64, 48, DI, false, false>(g_hid, W, g_sp, nullptr, nullptr);
}
__global__ void __launch_bounds__(512) gemm_out_k(const float* __restrict__ W) {
    gemm128_body<128, DM, DI, true, false>(g_y, W, g_h, g_h, nullptr);
}

// ---------------- embed ----------------
__global__ void embed_kernel(const float* __restrict__ x,
                             const float* __restrict__ pos,
                             const float* __restrict__ We,
                             const float* __restrict__ be) {
    int row = blockIdx.x;
    int j   = threadIdx.x;
    int l   = row & (L_-1);
    float x0 = x[row*2+0], x1 = x[row*2+1];
    g_h[(size_t)row*DM + j]       = x0*We[j] + x1*We[128+j] + be[j];
    g_h[(size_t)row*DM + 128 + j] = pos[l*128 + j];
}

// ---------------- causal depthwise conv (K=4) + silu, float4 (R13) ----------------
__global__ void __launch_bounds__(256) conv_silu_kernel(const float* __restrict__ cw,
                                                        const float* __restrict__ cb) {
    int idx  = blockIdx.x*256 + threadIdx.x;     // over ROWS*(DI/4)
    int d    = (idx & 127) * 4;
    int row  = idx >> 7;
    int l    = row & (L_-1);
    const float* base = g_hidgate + (size_t)row*(2*DI) + d;
    float4 w0 = *reinterpret_cast<const float4*>(cw + (d+0)*KC);
    float4 w1 = *reinterpret_cast<const float4*>(cw + (d+1)*KC);
    float4 w2 = *reinterpret_cast<const float4*>(cw + (d+2)*KC);
    float4 w3 = *reinterpret_cast<const float4*>(cw + (d+3)*KC);
    float4 bias = *reinterpret_cast<const float4*>(cb + d);
    const float4 zero = make_float4(0.f, 0.f, 0.f, 0.f);
    float4 x3 = (l >= 3) ? *reinterpret_cast<const float4*>(base - 3*2*DI) : zero;
    float4 x2 = (l >= 2) ? *reinterpret_cast<const float4*>(base - 2*2*DI) : zero;
    float4 x1 = (l >= 1) ? *reinterpret_cast<const float4*>(base - 1*2*DI) : zero;
    float4 x0 = *reinterpret_cast<const float4*>(base);
    float4 acc;
    acc.x = fmaf(x0.x, w0.w, fmaf(x1.x, w0.z, fmaf(x2.x, w0.y, fmaf(x3.x, w0.x, bias.x))));
    acc.y = fmaf(x0.y, w1.w, fmaf(x1.y, w1.z, fmaf(x2.y, w1.y, fmaf(x3.y, w1.x, bias.y))));
    acc.z = fmaf(x0.z, w2.w, fmaf(x1.z, w2.z, fmaf(x2.z, w2.y, fmaf(x3.z, w2.x, bias.z))));
    acc.w = fmaf(x0.w, w3.w, fmaf(x1.w, w3.z, fmaf(x2.w, w3.y, fmaf(x3.w, w3.x, bias.w))));
    float4 r;
    r.x = acc.x / (1.f + __expf(-acc.x));
    r.y = acc.y / (1.f + __expf(-acc.y));
    r.z = acc.z / (1.f + __expf(-acc.z));
    r.w = acc.w / (1.f + __expf(-acc.w));
    *reinterpret_cast<float4*>(g_hid + (size_t)row*DI + d) = r;
}

// ---------------- scan pass 1: summaries; computes + stores delta ----------------
#define CH 16
__global__ void __launch_bounds__(256) scan_seg1(const float* __restrict__ Alog,
                                                 const float* __restrict__ Wdt,
                                                 const float* __restrict__ bdt) {
    const int s    = blockIdx.x & (SEG-1);
    const int dblk = (blockIdx.x >> 3) & 31;
    const int b    = blockIdx.x >> 8;
    const int tid  = threadIdx.x;
    const int n    = tid & 15;
    const int dl   = tid >> 4;
    const int d    = dblk*16 + dl;
    const float A  = -__expf(Alog[d*NS + n]);
    float h = 0.f, P = 1.f;
    __shared__ float s_Wdt[DTR][17], s_bdt[16];
    __shared__ float s_dt[CH][16], s_delta[CH][16], s_hid[CH][16], s_B[CH][16];
    {
        int r = tid >> 4, c = tid & 15;
        s_Wdt[r][c] = Wdt[r*DI + dblk*16 + c];
        if (tid < 16) s_bdt[tid] = bdt[dblk*16 + tid];
    }
    __syncthreads();
    const int tbase = b*L_ + s*SEGLEN;
    for (int t0 = 0; t0 < SEGLEN; t0 += CH) {
        __syncthreads();
        {
            int tt = tid >> 4, c = tid & 15;
            int row = tbase + t0 + tt;
            s_dt[tt][c]  = g_sp[row*48 + c];
            s_hid[tt][c] = g_hid[(size_t)row*DI + dblk*16 + c];
            s_B[tt][c]   = g_sp[row*48 + DTR + c];
        }
        __syncthreads();
        {
            int tt = tid >> 4, c = tid & 15;
            float acc = s_bdt[c];
            #pragma unroll
            for (int r = 0; r < DTR; r++) acc = fmaf(s_dt[tt][r], s_Wdt[r][c], acc);
            float de = (acc > 20.f) ? acc : log1pf(__expf(acc));
            s_delta[tt][c] = de;
            int row = tbase + t0 + tt;
            g_delta[(size_t)row*DI + dblk*16 + c] = de;
        }
        __syncthreads();
        #pragma unroll
        for (int tt = 0; tt < CH; tt++) {
            float de  = s_delta[tt][dl];
            float dA  = __expf(de * A);
            float dBu = de * s_B[tt][n] * s_hid[tt][dl];
            h = fmaf(dA, h, dBu);
            P *= dA;
        }
    }
    int idx = ((b*32 + dblk)*SEG + s)*256 + tid;
    g_segP[idx] = P;
    g_segH[idx] = h;
}

// ---------------- scan pass 2: replay; delta loaded; emits y ----------------
__global__ void __launch_bounds__(256) scan_seg2(const float* __restrict__ Alog,
                                                 const float* __restrict__ Dsk) {
    const int s    = blockIdx.x & (SEG-1);
    const int dblk = (blockIdx.x >> 3) & 31;
    const int b    = blockIdx.x >> 8;
    const int tid  = threadIdx.x;
    const int n    = tid & 15;
    const int dl   = tid >> 4;
    const int d    = dblk*16 + dl;
    const float A  = -__expf(Alog[d*NS + n]);
    const float Dskip = Dsk[d];

    float h = 0.f;
    {
        const int base = (b*32 + dblk)*SEG;
        float Ps[SEG-1], Hs[SEG-1];
        #pragma unroll
        for (int ss = 0; ss < SEG-1; ss++) {
            if (ss < s) {
                int idx = (base + ss)*256 + tid;
                Ps[ss] = g_segP[idx];
                Hs[ss] = g_segH[idx];
            }
        }
        #pragma unroll
        for (int ss = 0; ss < SEG-1; ss++)
            if (ss < s) h = fmaf(Ps[ss], h, Hs[ss]);
    }

    __shared__ float s_delta[CH][16], s_hid[CH][16], s_B[CH][16],
                     s_C[CH][16], s_gate[CH][16], s_y[CH][16];
    const int tbase = b*L_ + s*SEGLEN;
    for (int t0 = 0; t0 < SEGLEN; t0 += CH) {
        __syncthreads();
        {
            int tt = tid >> 4, c = tid & 15;
            int row = tbase + t0 + tt;
            s_delta[tt][c] = g_delta[(size_t)row*DI + dblk*16 + c];
            s_hid[tt][c]   = g_hid[(size_t)row*DI + dblk*16 + c];
            s_B[tt][c]     = g_sp[row*48 + DTR + c];
            s_C[tt][c]     = g_sp[row*48 + DTR + NS + c];
            s_gate[tt][c]  = g_hidgate[(size_t)row*(2*DI) + DI + dblk*16 + c];
        }
        __syncthreads();
        #pragma unroll
        for (int tt = 0; tt < CH; tt++) {
            float de  = s_delta[tt][dl];
            float dA  = __expf(de * A);
            float dBu = de * s_B[tt][n] * s_hid[tt][dl];
            h = fmaf(dA, h, dBu);
            float contrib = h * s_C[tt][n];
            contrib += __shfl_xor_sync(0xffffffffu, contrib, 1);
            contrib += __shfl_xor_sync(0xffffffffu, contrib, 2);
            contrib += __shfl_xor_sync(0xffffffffu, contrib, 4);
            contrib += __shfl_xor_sync(0xffffffffu, contrib, 8);
            if (n == 0) {
                float yv = contrib + s_hid[tt][dl]*Dskip;
                float g  = s_gate[tt][dl];
                s_y[tt][dl] = yv * g / (1.f + __expf(-g));
            }
        }
        __syncthreads();
        {
            int tt = tid >> 4, c = tid & 15;
            int row = tbase + t0 + tt;
            g_y[(size_t)row*DI + dblk*16 + c] = s_y[tt][c];
        }
    }
}

// ---------------- output head ----------------
__global__ void __launch_bounds__(256) head_kernel(const float* __restrict__ Wa,
                                                   const float* __restrict__ ba,
                                                   const float* __restrict__ Wp,
                                                   const float* __restrict__ bp,
                                                   float* __restrict__ out) {
    int row = blockIdx.x, tid = threadIdx.x;
    float v  = g_h[(size_t)row*DM + tid];
    float pa = v * Wa[tid];
    float pp = v * Wp[tid];
    #pragma unroll
    for (int o = 16; o > 0; o >>= 1) {
        pa += __shfl_xor_sync(0xffffffffu, pa, o);
        pp += __shfl_xor_sync(0xffffffffu, pp, o);
    }
    __shared__ float ra[8], rp[8];
    if ((tid & 31) == 0) { ra[tid>>5] = pa; rp[tid>>5] = pp; }
    __syncthreads();
    if (tid == 0) {
        float sa = 0.f, sp2 = 0.f;
        #pragma unroll
        for (int i = 0; i < 8; i++) { sa += ra[i]; sp2 += rp[i]; }
        out[row*2+0] = sa + ba[0];
        out[row*2+1] = tanhf(sp2 + bp[0]);
    }
}

// ---------------- launch ----------------
extern "C" void kernel_launch(void* const* d_in, const int* in_sizes, int n_in,
                              void* d_out, int out_size) {
    const float* x       = (const float*)d_in[0];
    const float* pos     = (const float*)d_in[1];
    const float* W_embed = (const float*)d_in[2];
    const float* b_embed = (const float*)d_in[3];
    const float* ln_w    = (const float*)d_in[4];
    const float* W_in    = (const float*)d_in[5];
    const float* conv_w  = (const float*)d_in[6];
    const float* conv_b  = (const float*)d_in[7];
    const float* W_x     = (const float*)d_in[8];
    const float* W_dt    = (const float*)d_in[9];
    const float* b_dt    = (const float*)d_in[10];
    const float* A_log   = (const float*)d_in[11];
    const float* D_skip  = (const float*)d_in[12];
    const float* W_out   = (const float*)d_in[13];
    const float* W_amp   = (const float*)d_in[14];
    const float* b_amp   = (const float*)d_in[15];
    const float* W_phase = (const float*)d_in[16];
    const float* b_phase = (const float*)d_in[17];

    embed_kernel<<<ROWS, 128>>>(x, pos, W_embed, b_embed);

    for (int i = 0; i < NL; i++) {
        gemm_in_k<<<dim3((2*DI)/128, ROWS/128), 512>>>(W_in + (size_t)i*DM*2*DI,
                                                       ln_w + (size_t)i*DM);
        conv_silu_kernel<<<(ROWS*DI/4)/256, 256>>>(conv_w + (size_t)i*DI*KC,
                                                   conv_b + (size_t)i*DI);
        gemm_x_k<<<dim3(1, ROWS/128), 512>>>(W_x + (size_t)i*DI*48);
        scan_seg1<<<B_*32*SEG, 256>>>(A_log + (size_t)i*DI*NS,
                                      W_dt + (size_t)i*DTR*DI,
                                      b_dt + (size_t)i*DI);
        scan_seg2<<<B_*32*SEG, 256>>>(A_log + (size_t)i*DI*NS,
                                      D_skip + (size_t)i*DI);
        gemm_out_k<<<dim3(DM/128, ROWS/128), 512>>>(W_out + (size_t)i*DI*DM);
    }

    head_kernel<<<ROWS, 256>>>(W_amp, b_amp, W_phase, b_phase, (float*)d_out);
}

// round 17
// speedup vs baseline: 1.2620x; 1.1970x over previous
#include <cuda_runtime.h>
#include <cuda_fp16.h>
#include <math.h>
#include <stdint.h>

#define B_   4
#define L_   1024
#define DM   256
#define DI   512
#define NS   16
#define DTR  16
#define KC   4
#define NL   8
#define ROWS (B_*L_)
#define SEG  8
#define SEGLEN (L_/SEG)   // 128
#define KSPL 4            // split-K factor for gemm_x

// ---------------- static scratch (no allocs allowed) ----------------
__device__ float g_h[ROWS*DM];        // residual stream
__device__ float g_hidgate[ROWS*2*DI];// in-proj output: [hid | gate]
__device__ float g_hid[ROWS*DI];      // post conv+silu
__device__ float g_sp[ROWS*48];       // [dt(16) | B(16) | C(16)]
__device__ float g_spPart[KSPL*ROWS*48]; // split-K partials for gemm_x
__device__ float g_delta[ROWS*DI];    // softplus(dt@Wdt+b), seg1 -> seg2
__device__ float g_y[ROWS*DI];        // scan output (gated)
__device__ float g_segP[B_*32*SEG*256];
__device__ float g_segH[B_*32*SEG*256];

// ---------------- f16-split helpers (identical to R14/R16) ----------------
#define LO_SCALE    2048.0f
#define LO_UNSCALE  (1.0f/2048.0f)

__device__ __forceinline__ uint32_t pack_h2(float x, float y) {
    __half2 h = __floats2half2_rn(x, y);
    return *reinterpret_cast<uint32_t*>(&h);
}
__device__ __forceinline__ void split_f16(float x, float& hi, float& lo) {
    hi = __half2float(__float2half_rn(x));
    lo = (x - hi) * LO_SCALE;
}
__device__ __forceinline__ void mma_f16(float* c,
                                        uint32_t a0, uint32_t a1, uint32_t a2, uint32_t a3,
                                        uint32_t b0, uint32_t b1) {
    asm volatile(
        "mma.sync.aligned.m16n8k16.row.col.f32.f16.f16.f32 "
        "{%0,%1,%2,%3}, {%4,%5,%6,%7}, {%8,%9}, {%0,%1,%2,%3};"
        : "+f"(c[0]), "+f"(c[1]), "+f"(c[2]), "+f"(c[3])
        : "r"(a0), "r"(a1), "r"(a2), "r"(a3), "r"(b0), "r"(b1));
}

__device__ __forceinline__ void stage_A_word(uint32_t (*Ash)[20], uint32_t (*Asl)[20],
                                             int r, int k4, float4 v) {
    float hx,lx,hy,ly,hz,lz,hw,lw;
    split_f16(v.x, hx, lx);
    split_f16(v.y, hy, ly);
    split_f16(v.z, hz, lz);
    split_f16(v.w, hw, lw);
    Ash[r][k4*2    ] = pack_h2(hx, hy);
    Ash[r][k4*2 + 1] = pack_h2(hz, hw);
    Asl[r][k4*2    ] = pack_h2(lx, ly);
    Asl[r][k4*2 + 1] = pack_h2(lz, lw);
}

// ================= 128xBN f16-split GEMM, 512 threads, reg-prefetch =================
// C[M,N_] = A[M,K_ slice] @ W[K_,N_] (+Res). Warp grid 4x4.
// k range [k_begin, k_end); col0 passed in (supports split-K wrappers).
template<int BN, int N_, int K_, bool RES, bool DO_RMS>
__device__ __forceinline__ void gemm128_body(const float* __restrict__ A,
                                             const float* __restrict__ W,
                                             float* C, const float* Res,
                                             const float* lnw,
                                             int col0, int k_begin, int k_end) {
    constexpr int NT  = BN / 32;
    constexpr int BIT = (8*BN)/512;    // B prefetch iterations
    __shared__ uint32_t Ash[128][20], Asl[128][20];
    __shared__ uint32_t Bsh[BN][20],  Bsl[BN][20];
    __shared__ float sScale[128];
    __shared__ float sW[DM];
    const int tid  = threadIdx.x;      // 0..511
    const int lane = tid & 31;
    const int warp = tid >> 5;         // 0..15
    const int wr   = warp & 3;
    const int wc   = warp >> 2;
    const int g    = lane >> 2;
    const int t    = lane & 3;
    const int row0 = blockIdx.y * 128;

    if (DO_RMS) {
        if (tid < DM) sW[tid] = lnw[tid];
        #pragma unroll
        for (int i = 0; i < 8; i++) {
            int r = warp*8 + i;
            const float* src = A + (size_t)(row0 + r) * DM;
            float4 v0 = *reinterpret_cast<const float4*>(src + lane * 4);
            float4 v1 = *reinterpret_cast<const float4*>(src + 128 + lane * 4);
            float ss = v0.x*v0.x + v0.y*v0.y + v0.z*v0.z + v0.w*v0.w
                     + v1.x*v1.x + v1.y*v1.y + v1.z*v1.z + v1.w*v1.w;
            #pragma unroll
            for (int o = 16; o > 0; o >>= 1) ss += __shfl_xor_sync(0xffffffffu, ss, o);
            if (lane == 0) sScale[r] = rsqrtf(ss * (1.f/DM) + 1e-5f);
        }
        __syncthreads();
    }

    float acc[2][NT][4], acc2[2][NT][4];
    #pragma unroll
    for (int mt = 0; mt < 2; mt++)
        #pragma unroll
        for (int nt = 0; nt < NT; nt++)
            #pragma unroll
            for (int q = 0; q < 4; q++) { acc[mt][nt][q] = 0.f; acc2[mt][nt][q] = 0.f; }

    // ---- register prefetch buffers ----
    float4 pA[2];
    float2 pB0[BIT], pB1[BIT];

    auto loadA = [&](int k0) {
        #pragma unroll
        for (int it = 0; it < 2; it++) {
            int idx = tid + it*512;
            int r = idx >> 3, k4 = idx & 7;
            pA[it] = *reinterpret_cast<const float4*>(
                A + (size_t)(row0 + r)*K_ + k0 + k4*4);
        }
    };
    auto loadB = [&](int k0) {
        #pragma unroll
        for (int it = 0; it < BIT; it++) {
            int idx = tid + it*512;
            int kp = idx & 15, np = idx >> 4;
            int gn = col0 + np*2;
            if ((N_ % BN) == 0 || gn < N_) {
                pB0[it] = *reinterpret_cast<const float2*>(W + (size_t)(k0 + 2*kp    )*N_ + gn);
                pB1[it] = *reinterpret_cast<const float2*>(W + (size_t)(k0 + 2*kp + 1)*N_ + gn);
            } else {
                pB0[it] = make_float2(0.f, 0.f);
                pB1[it] = pB0[it];
            }
        }
    };

    loadA(k_begin);
    loadB(k_begin);

    for (int k0 = k_begin; k0 < k_end; k0 += 32) {
        // ---- store prefetched regs to smem (with split; rms applied here) ----
        #pragma unroll
        for (int it = 0; it < 2; it++) {
            int idx = tid + it*512;
            int r = idx >> 3, k4 = idx & 7;
            float4 v = pA[it];
            if (DO_RMS) {
                float sc = sScale[r];
                v.x = v.x * sc * sW[k0 + k4*4 + 0];
                v.y = v.y * sc * sW[k0 + k4*4 + 1];
                v.z = v.z * sc * sW[k0 + k4*4 + 2];
                v.w = v.w * sc * sW[k0 + k4*4 + 3];
            }
            stage_A_word(Ash, Asl, r, k4, v);
        }
        #pragma unroll
        for (int it = 0; it < BIT; it++) {
            int idx = tid + it*512;
            int kp = idx & 15, np = idx >> 4;
            float2 v0 = pB0[it], v1 = pB1[it];
            float h00,l00,h10,l10,h01,l01,h11,l11;
            split_f16(v0.x, h00, l00);
            split_f16(v1.x, h10, l10);
            split_f16(v0.y, h01, l01);
            split_f16(v1.y, h11, l11);
            Bsh[np*2    ][kp] = pack_h2(h00, h10);
            Bsh[np*2 + 1][kp] = pack_h2(h01, h11);
            Bsl[np*2    ][kp] = pack_h2(l00, l10);
            Bsl[np*2 + 1][kp] = pack_h2(l01, l11);
        }
        __syncthreads();

        // ---- issue next chunk's loads (overlap with mainloop) ----
        if (k0 + 32 < k_end) {
            loadA(k0 + 32);
            loadB(k0 + 32);
        }

        // ---- mainloop ----
        #pragma unroll
        for (int ks = 0; ks < 2; ks++) {
            const int kb = ks*8 + t;
            #pragma unroll
            for (int mt = 0; mt < 2; mt++) {
                const int rb = wr*32 + mt*16 + g;
                uint32_t ah0 = Ash[rb    ][kb    ], ah1 = Ash[rb + 8][kb    ];
                uint32_t ah2 = Ash[rb    ][kb + 4], ah3 = Ash[rb + 8][kb + 4];
                uint32_t al0 = Asl[rb    ][kb    ], al1 = Asl[rb + 8][kb    ];
                uint32_t al2 = Asl[rb    ][kb + 4], al3 = Asl[rb + 8][kb + 4];
                #pragma unroll
                for (int nt = 0; nt < NT; nt++) {
                    const int cb = wc*(BN/4) + nt*8 + g;
                    uint32_t bh0 = Bsh[cb][kb], bh1 = Bsh[cb][kb + 4];
                    uint32_t bl0 = Bsl[cb][kb], bl1 = Bsl[cb][kb + 4];
                    mma_f16(acc [mt][nt], ah0, ah1, ah2, ah3, bh0, bh1);
                    mma_f16(acc2[mt][nt], ah0, ah1, ah2, ah3, bl0, bl1);
                    mma_f16(acc2[mt][nt], al0, al1, al2, al3, bh0, bh1);
                }
            }
        }
        __syncthreads();
    }

    // ---- epilogue ----
    #pragma unroll
    for (int mt = 0; mt < 2; mt++) {
        const int r0 = row0 + wr*32 + mt*16 + g;
        #pragma unroll
        for (int nt = 0; nt < NT; nt++) {
            const int cbase = col0 + wc*(BN/4) + nt*8 + 2*t;
            #pragma unroll
            for (int h = 0; h < 2; h++) {
                int gm = r0 + h*8;
                #pragma unroll
                for (int q = 0; q < 2; q++) {
                    int gn = cbase + q;
                    if ((N_ % BN) == 0 || gn < N_) {
                        float v = fmaf(acc2[mt][nt][h*2 + q], LO_UNSCALE, acc[mt][nt][h*2 + q]);
                        if (RES) v += Res[(size_t)gm*N_ + gn];
                        C[(size_t)gm*N_ + gn] = v;
                    }
                }
            }
        }
    }
}

__global__ void __launch_bounds__(512) gemm_in_k(const float* __restrict__ W,
                                                 const float* __restrict__ lnw) {
    gemm128_body<128, 2*DI, DM, false, true>(g_h, W, g_hidgate, nullptr, lnw,
                                             blockIdx.x * 128, 0, DM);
}
// gemm_x: blockIdx.x = K-split index; each split covers K/KSPL = 128
__global__ void __launch_bounds__(512) gemm_x_k(const float* __restrict__ W) {
    const int ks = blockIdx.x;
    gemm128_body<64, 48, DI, false, false>(g_hid, W,
        g_spPart + (size_t)ks * ROWS * 48, nullptr, nullptr,
        0, ks * (DI/KSPL), (ks + 1) * (DI/KSPL));
}
__global__ void __launch_bounds__(512) gemm_out_k(const float* __restrict__ W) {
    gemm128_body<64, DM, DI, true, false>(g_y, W, g_h, g_h, nullptr,
                                          blockIdx.x * 64, 0, DI);
}

// ---------------- split-K combine (fixed order, deterministic) ----------------
__global__ void __launch_bounds__(256) spk_combine_kernel() {
    int i = blockIdx.x*256 + threadIdx.x;      // over ROWS*48/4 float4s
    const float4* p0 = reinterpret_cast<const float4*>(g_spPart) + i;
    const float4* p1 = reinterpret_cast<const float4*>(g_spPart + (size_t)ROWS*48) + i;
    const float4* p2 = reinterpret_cast<const float4*>(g_spPart + (size_t)2*ROWS*48) + i;
    const float4* p3 = reinterpret_cast<const float4*>(g_spPart + (size_t)3*ROWS*48) + i;
    float4 a = *p0, b = *p1, c = *p2, d = *p3;
    float4 r;
    r.x = ((a.x + b.x) + c.x) + d.x;
    r.y = ((a.y + b.y) + c.y) + d.y;
    r.z = ((a.z + b.z) + c.z) + d.z;
    r.w = ((a.w + b.w) + c.w) + d.w;
    reinterpret_cast<float4*>(g_sp)[i] = r;
}

// ---------------- embed ----------------
__global__ void embed_kernel(const float* __restrict__ x,
                             const float* __restrict__ pos,
                             const float* __restrict__ We,
                             const float* __restrict__ be) {
    int row = blockIdx.x;
    int j   = threadIdx.x;
    int l   = row & (L_-1);
    float x0 = x[row*2+0], x1 = x[row*2+1];
    g_h[(size_t)row*DM + j]       = x0*We[j] + x1*We[128+j] + be[j];
    g_h[(size_t)row*DM + 128 + j] = pos[l*128 + j];
}

// ---------------- causal depthwise conv (K=4) + silu, float4 (R13) ----------------
__global__ void __launch_bounds__(256) conv_silu_kernel(const float* __restrict__ cw,
                                                        const float* __restrict__ cb) {
    int idx  = blockIdx.x*256 + threadIdx.x;     // over ROWS*(DI/4)
    int d    = (idx & 127) * 4;
    int row  = idx >> 7;
    int l    = row & (L_-1);
    const float* base = g_hidgate + (size_t)row*(2*DI) + d;
    float4 w0 = *reinterpret_cast<const float4*>(cw + (d+0)*KC);
    float4 w1 = *reinterpret_cast<const float4*>(cw + (d+1)*KC);
    float4 w2 = *reinterpret_cast<const float4*>(cw + (d+2)*KC);
    float4 w3 = *reinterpret_cast<const float4*>(cw + (d+3)*KC);
    float4 bias = *reinterpret_cast<const float4*>(cb + d);
    const float4 zero = make_float4(0.f, 0.f, 0.f, 0.f);
    float4 x3 = (l >= 3) ? *reinterpret_cast<const float4*>(base - 3*2*DI) : zero;
    float4 x2 = (l >= 2) ? *reinterpret_cast<const float4*>(base - 2*2*DI) : zero;
    float4 x1 = (l >= 1) ? *reinterpret_cast<const float4*>(base - 1*2*DI) : zero;
    float4 x0 = *reinterpret_cast<const float4*>(base);
    float4 acc;
    acc.x = fmaf(x0.x, w0.w, fmaf(x1.x, w0.z, fmaf(x2.x, w0.y, fmaf(x3.x, w0.x, bias.x))));
    acc.y = fmaf(x0.y, w1.w, fmaf(x1.y, w1.z, fmaf(x2.y, w1.y, fmaf(x3.y, w1.x, bias.y))));
    acc.z = fmaf(x0.z, w2.w, fmaf(x1.z, w2.z, fmaf(x2.z, w2.y, fmaf(x3.z, w2.x, bias.z))));
    acc.w = fmaf(x0.w, w3.w, fmaf(x1.w, w3.z, fmaf(x2.w, w3.y, fmaf(x3.w, w3.x, bias.w))));
    float4 r;
    r.x = acc.x / (1.f + __expf(-acc.x));
    r.y = acc.y / (1.f + __expf(-acc.y));
    r.z = acc.z / (1.f + __expf(-acc.z));
    r.w = acc.w / (1.f + __expf(-acc.w));
    *reinterpret_cast<float4*>(g_hid + (size_t)row*DI + d) = r;
}

// ---------------- scan pass 1: summaries; computes + stores delta ----------------
#define CH 16
__global__ void __launch_bounds__(256) scan_seg1(const float* __restrict__ Alog,
                                                 const float* __restrict__ Wdt,
                                                 const float* __restrict__ bdt) {
    const int s    = blockIdx.x & (SEG-1);
    const int dblk = (blockIdx.x >> 3) & 31;
    const int b    = blockIdx.x >> 8;
    const int tid  = threadIdx.x;
    const int n    = tid & 15;
    const int dl   = tid >> 4;
    const int d    = dblk*16 + dl;
    const float A  = -__expf(Alog[d*NS + n]);
    float h = 0.f, P = 1.f;
    __shared__ float s_Wdt[DTR][17], s_bdt[16];
    __shared__ float s_dt[CH][16], s_delta[CH][16], s_hid[CH][16], s_B[CH][16];
    {
        int r = tid >> 4, c = tid & 15;
        s_Wdt[r][c] = Wdt[r*DI + dblk*16 + c];
        if (tid < 16) s_bdt[tid] = bdt[dblk*16 + tid];
    }
    __syncthreads();
    const int tbase = b*L_ + s*SEGLEN;
    for (int t0 = 0; t0 < SEGLEN; t0 += CH) {
        __syncthreads();
        {
            int tt = tid >> 4, c = tid & 15;
            int row = tbase + t0 + tt;
            s_dt[tt][c]  = g_sp[row*48 + c];
            s_hid[tt][c] = g_hid[(size_t)row*DI + dblk*16 + c];
            s_B[tt][c]   = g_sp[row*48 + DTR + c];
        }
        __syncthreads();
        {
            int tt = tid >> 4, c = tid & 15;
            float acc = s_bdt[c];
            #pragma unroll
            for (int r = 0; r < DTR; r++) acc = fmaf(s_dt[tt][r], s_Wdt[r][c], acc);
            float de = (acc > 20.f) ? acc : log1pf(__expf(acc));
            s_delta[tt][c] = de;
            int row = tbase + t0 + tt;
            g_delta[(size_t)row*DI + dblk*16 + c] = de;
        }
        __syncthreads();
        #pragma unroll
        for (int tt = 0; tt < CH; tt++) {
            float de  = s_delta[tt][dl];
            float dA  = __expf(de * A);
            float dBu = de * s_B[tt][n] * s_hid[tt][dl];
            h = fmaf(dA, h, dBu);
            P *= dA;
        }
    }
    int idx = ((b*32 + dblk)*SEG + s)*256 + tid;
    g_segP[idx] = P;
    g_segH[idx] = h;
}

// ---------------- scan pass 2: replay; delta loaded; emits y ----------------
__global__ void __launch_bounds__(256) scan_seg2(const float* __restrict__ Alog,
                                                 const float* __restrict__ Dsk) {
    const int s    = blockIdx.x & (SEG-1);
    const int dblk = (blockIdx.x >> 3) & 31;
    const int b    = blockIdx.x >> 8;
    const int tid  = threadIdx.x;
    const int n    = tid & 15;
    const int dl   = tid >> 4;
    const int d    = dblk*16 + dl;
    const float A  = -__expf(Alog[d*NS + n]);
    const float Dskip = Dsk[d];

    float h = 0.f;
    {
        const int base = (b*32 + dblk)*SEG;
        float Ps[SEG-1], Hs[SEG-1];
        #pragma unroll
        for (int ss = 0; ss < SEG-1; ss++) {
            if (ss < s) {
                int idx = (base + ss)*256 + tid;
                Ps[ss] = g_segP[idx];
                Hs[ss] = g_segH[idx];
            }
        }
        #pragma unroll
        for (int ss = 0; ss < SEG-1; ss++)
            if (ss < s) h = fmaf(Ps[ss], h, Hs[ss]);
    }

    __shared__ float s_delta[CH][16], s_hid[CH][16], s_B[CH][16],
                     s_C[CH][16], s_gate[CH][16], s_y[CH][16];
    const int tbase = b*L_ + s*SEGLEN;
    for (int t0 = 0; t0 < SEGLEN; t0 += CH) {
        __syncthreads();
        {
            int tt = tid >> 4, c = tid & 15;
            int row = tbase + t0 + tt;
            s_delta[tt][c] = g_delta[(size_t)row*DI + dblk*16 + c];
            s_hid[tt][c]   = g_hid[(size_t)row*DI + dblk*16 + c];
            s_B[tt][c]     = g_sp[row*48 + DTR + c];
            s_C[tt][c]     = g_sp[row*48 + DTR + NS + c];
            s_gate[tt][c]  = g_hidgate[(size_t)row*(2*DI) + DI + dblk*16 + c];
        }
        __syncthreads();
        #pragma unroll
        for (int tt = 0; tt < CH; tt++) {
            float de  = s_delta[tt][dl];
            float dA  = __expf(de * A);
            float dBu = de * s_B[tt][n] * s_hid[tt][dl];
            h = fmaf(dA, h, dBu);
            float contrib = h * s_C[tt][n];
            contrib += __shfl_xor_sync(0xffffffffu, contrib, 1);
            contrib += __shfl_xor_sync(0xffffffffu, contrib, 2);
            contrib += __shfl_xor_sync(0xffffffffu, contrib, 4);
            contrib += __shfl_xor_sync(0xffffffffu, contrib, 8);
            if (n == 0) {
                float yv = contrib + s_hid[tt][dl]*Dskip;
                float g  = s_gate[tt][dl];
                s_y[tt][dl] = yv * g / (1.f + __expf(-g));
            }
        }
        __syncthreads();
        {
            int tt = tid >> 4, c = tid & 15;
            int row = tbase + t0 + tt;
            g_y[(size_t)row*DI + dblk*16 + c] = s_y[tt][c];
        }
    }
}

// ---------------- output head ----------------
__global__ void __launch_bounds__(256) head_kernel(const float* __restrict__ Wa,
                                                   const float* __restrict__ ba,
                                                   const float* __restrict__ Wp,
                                                   const float* __restrict__ bp,
                                                   float* __restrict__ out) {
    int row = blockIdx.x, tid = threadIdx.x;
    float v  = g_h[(size_t)row*DM + tid];
    float pa = v * Wa[tid];
    float pp = v * Wp[tid];
    #pragma unroll
    for (int o = 16; o > 0; o >>= 1) {
        pa += __shfl_xor_sync(0xffffffffu, pa, o);
        pp += __shfl_xor_sync(0xffffffffu, pp, o);
    }
    __shared__ float ra[8], rp[8];
    if ((tid & 31) == 0) { ra[tid>>5] = pa; rp[tid>>5] = pp; }
    __syncthreads();
    if (tid == 0) {
        float sa = 0.f, sp2 = 0.f;
        #pragma unroll
        for (int i = 0; i < 8; i++) { sa += ra[i]; sp2 += rp[i]; }
        out[row*2+0] = sa + ba[0];
        out[row*2+1] = tanhf(sp2 + bp[0]);
    }
}

// ---------------- launch ----------------
extern "C" void kernel_launch(void* const* d_in, const int* in_sizes, int n_in,
                              void* d_out, int out_size) {
    const float* x       = (const float*)d_in[0];
    const float* pos     = (const float*)d_in[1];
    const float* W_embed = (const float*)d_in[2];
    const float* b_embed = (const float*)d_in[3];
    const float* ln_w    = (const float*)d_in[4];
    const float* W_in    = (const float*)d_in[5];
    const float* conv_w  = (const float*)d_in[6];
    const float* conv_b  = (const float*)d_in[7];
    const float* W_x     = (const float*)d_in[8];
    const float* W_dt    = (const float*)d_in[9];
    const float* b_dt    = (const float*)d_in[10];
    const float* A_log   = (const float*)d_in[11];
    const float* D_skip  = (const float*)d_in[12];
    const float* W_out   = (const float*)d_in[13];
    const float* W_amp   = (const float*)d_in[14];
    const float* b_amp   = (const float*)d_in[15];
    const float* W_phase = (const float*)d_in[16];
    const float* b_phase = (const float*)d_in[17];

    embed_kernel<<<ROWS, 128>>>(x, pos, W_embed, b_embed);

    for (int i = 0; i < NL; i++) {
        gemm_in_k<<<dim3((2*DI)/128, ROWS/128), 512>>>(W_in + (size_t)i*DM*2*DI,
                                                       ln_w + (size_t)i*DM);
        conv_silu_kernel<<<(ROWS*DI/4)/256, 256>>>(conv_w + (size_t)i*DI*KC,
                                                   conv_b + (size_t)i*DI);
        gemm_x_k<<<dim3(KSPL, ROWS/128), 512>>>(W_x + (size_t)i*DI*48);
        spk_combine_kernel<<<(ROWS*48/4)/256, 256>>>();
        scan_seg1<<<B_*32*SEG, 256>>>(A_log + (size_t)i*DI*NS,
                                      W_dt + (size_t)i*DTR*DI,
                                      b_dt + (size_t)i*DI);
        scan_seg2<<<B_*32*SEG, 256>>>(A_log + (size_t)i*DI*NS,
                                      D_skip + (size_t)i*DI);
        gemm_out_k<<<dim3(DM/64, ROWS/128), 512>>>(W_out + (size_t)i*DI*DM);
    }

    head_kernel<<<ROWS, 256>>>(W_amp, b_amp, W_phase, b_phase, (float*)d_out);
}